// round 15
// baseline (speedup 1.0000x reference)
#include <cuda_runtime.h>
#include <cuda_bf16.h>
#include <cstdint>

// ---------------------------------------------------------------------------
// Problem constants
// ---------------------------------------------------------------------------
constexpr int N_ROWS = 32768;
constexpr int D      = 1024;
constexpr int TWO_D  = 2048;
constexpr int A_DIM  = 256;
constexpr int FD     = 64;          // gate linear out width
constexpr int R_TILE = 8;           // rows per CTA (mega kernel)
constexpr int KC     = 64;          // k per chunk
constexpr int NCHUNK = TWO_D / KC;  // 32
constexpr int APAD   = 72;          // B tile padded k-stride (bf16)
constexpr int USTRIDE = 1032;       // row-cache padded stride (bf16 elems)
constexpr float EPSF = 1e-5f;

// ---------------------------------------------------------------------------
// Device scratch (small!)
// ---------------------------------------------------------------------------
__device__ float g_aux_term[N_ROWS];                        // agw * rsig(aux_gate)
__device__ __align__(16) __nv_bfloat16 g_Wt[FD * TWO_D];    // W^T bf16 [n][k]

// ---------------------------------------------------------------------------
// Helpers (proven idioms only)
// ---------------------------------------------------------------------------
__device__ __forceinline__ float sigmoidf(float x) { return 1.0f / (1.0f + expf(-x)); }

__device__ __forceinline__ float rsigf(float x) {
    float y = fminf(fmaxf(x, 0.001f), 0.999f);
    return logf(y) - log1pf(-y);
}

__device__ __forceinline__ void mma16816(float* c, uint32_t a0, uint32_t a1,
                                         uint32_t a2, uint32_t a3,
                                         uint32_t b0, uint32_t b1) {
    asm volatile(
        "mma.sync.aligned.m16n8k16.row.col.f32.bf16.bf16.f32 "
        "{%0,%1,%2,%3}, {%4,%5,%6,%7}, {%8,%9}, {%0,%1,%2,%3};"
        : "+f"(c[0]), "+f"(c[1]), "+f"(c[2]), "+f"(c[3])
        : "r"(a0), "r"(a1), "r"(a2), "r"(a3), "r"(b0), "r"(b1));
}

// ---------------------------------------------------------------------------
// Kernel 1: W [2048,64] fp32 -> W^T bf16 [64][2048]   (verbatim proven)
// ---------------------------------------------------------------------------
__global__ void wconv_kernel(const float* __restrict__ W) {
    int idx = blockIdx.x * blockDim.x + threadIdx.x;
    if (idx >= FD * TWO_D) return;
    int n = idx >> 11;          // /2048
    int k = idx & 2047;
    g_Wt[idx] = __float2bfloat16(W[k * FD + n]);
}

// ---------------------------------------------------------------------------
// Kernel 2: aux path. Warp per row.   (verbatim proven)
// ---------------------------------------------------------------------------
__global__ __launch_bounds__(256) void aux_kernel(
    const float* __restrict__ aux, const float* __restrict__ gam,
    const float* __restrict__ bet, const float* __restrict__ Wa,
    const float* __restrict__ ba, const float* __restrict__ agw_p) {
    int wid = threadIdx.x >> 5, lane = threadIdx.x & 31;
    int row = blockIdx.x * 8 + wid;
    if (row >= N_ROWS) return;

    const float4* a4 = reinterpret_cast<const float4*>(aux + (size_t)row * A_DIM);
    float4 v0 = a4[lane];
    float4 v1 = a4[32 + lane];
    float vs[8] = {v0.x, v0.y, v0.z, v0.w, v1.x, v1.y, v1.z, v1.w};

    float s = 0.f, ss = 0.f;
#pragma unroll
    for (int i = 0; i < 8; i++) { s += vs[i]; ss += vs[i] * vs[i]; }
#pragma unroll
    for (int o = 16; o; o >>= 1) {
        s  += __shfl_xor_sync(0xFFFFFFFFu, s, o);
        ss += __shfl_xor_sync(0xFFFFFFFFu, ss, o);
    }
    float mu   = s * (1.0f / A_DIM);
    float var  = ss * (1.0f / A_DIM) - mu * mu;
    float rstd = rsqrtf(var + EPSF);

    float acc[8] = {0, 0, 0, 0, 0, 0, 0, 0};
#pragma unroll
    for (int i = 0; i < 8; i++) {
        int k = (i < 4) ? (lane * 4 + i) : (128 + lane * 4 + (i - 4));
        float xh = fmaxf((vs[i] - mu) * rstd * gam[k] + bet[k], 0.f);
        const float4* w4 = reinterpret_cast<const float4*>(Wa + k * 8);
        float4 wa = w4[0], wb = w4[1];
        acc[0] += xh * wa.x; acc[1] += xh * wa.y; acc[2] += xh * wa.z; acc[3] += xh * wa.w;
        acc[4] += xh * wb.x; acc[5] += xh * wb.y; acc[6] += xh * wb.z; acc[7] += xh * wb.w;
    }
#pragma unroll
    for (int o = 16; o; o >>= 1)
#pragma unroll
        for (int j = 0; j < 8; j++)
            acc[j] += __shfl_xor_sync(0xFFFFFFFFu, acc[j], o);

    if (lane == 0) {
        float sg = 0.f;
#pragma unroll
        for (int j = 0; j < 8; j++) sg += sigmoidf(acc[j] + ba[j]);
        float aux_gate = sg * (1.0f / 8.0f);
        g_aux_term[row] = (*agw_p) * rsigf(aux_gate);
    }
}

// ---------------------------------------------------------------------------
// Kernel 3: MEGA. 8 rows/CTA, 128 threads (4 warps). Static smem only.
// ---------------------------------------------------------------------------
__global__ __launch_bounds__(128)
void mega_kernel(const float* __restrict__ unary, const float* __restrict__ pair,
                 const float* __restrict__ gam, const float* __restrict__ bet,
                 const float* __restrict__ bias, const float* __restrict__ gw_p,
                 const float* __restrict__ aux_gw, float* __restrict__ out,
                 float* __restrict__ out_g) {
    __shared__ __align__(16) __nv_bfloat16 s_u[R_TILE * USTRIDE];  // 16512 B
    __shared__ __align__(16) __nv_bfloat16 s_p[R_TILE * USTRIDE];  // 16512 B
    __shared__ __align__(16) __nv_bfloat16 sB[FD * APAD];          //  9216 B
    __shared__ float s_mu[R_TILE], s_rstd[R_TILE], s_g[R_TILE];
    __shared__ float s_part[4][R_TILE], s_bias[FD];

    const int tid  = threadIdx.x;
    const int wid  = tid >> 5;     // 0..3
    const int lane = tid & 31;
    const int grp  = lane >> 2;    // 0..7
    const int tig  = lane & 3;     // 0..3
    const int m0   = blockIdx.x * R_TILE;

    if (tid < FD) s_bias[tid] = bias[tid];

    // ---- B prefetch chunk 0 (R13-proven geometry: 2 threads/row, 64B each) ----
    const int bn = tid >> 1;            // B row 0..63
    const int bq = (tid & 1) * 64;      // 64B half
    const char* bbase = reinterpret_cast<const char*>(g_Wt) + (size_t)bn * (TWO_D * 2) + bq;
    uint4 breg[4];
#pragma unroll
    for (int j = 0; j < 4; j++)
        breg[j] = *reinterpret_cast<const uint4*>(bbase + j * 16);

    // ---------------- Phase 1: rows -> relu -> bf16 cache + stats ----------
#pragma unroll
    for (int half = 0; half < 2; half++) {
        const int r = wid * 2 + half;
        const size_t grow = (size_t)(m0 + r);
        float s_acc = 0.f, ss_acc = 0.f;
#pragma unroll
        for (int t = 0; t < 2; t++) {
            const float4* src4 = reinterpret_cast<const float4*>(
                (t == 0 ? unary : pair) + grow * D);
            __nv_bfloat16* cache = (t == 0 ? s_u : s_p) + r * USTRIDE;
            float4 x[8];
#pragma unroll
            for (int j = 0; j < 8; j++) x[j] = src4[j * 32 + lane];
#pragma unroll
            for (int j = 0; j < 8; j++) {
                x[j].x = fmaxf(x[j].x, 0.f); s_acc += x[j].x; ss_acc += x[j].x * x[j].x;
                x[j].y = fmaxf(x[j].y, 0.f); s_acc += x[j].y; ss_acc += x[j].y * x[j].y;
                x[j].z = fmaxf(x[j].z, 0.f); s_acc += x[j].z; ss_acc += x[j].z * x[j].z;
                x[j].w = fmaxf(x[j].w, 0.f); s_acc += x[j].w; ss_acc += x[j].w * x[j].w;
            }
#pragma unroll
            for (int j = 0; j < 8; j++) {
                int k = 4 * (j * 32 + lane);
                *reinterpret_cast<__nv_bfloat162*>(&cache[k]) =
                    __floats2bfloat162_rn(x[j].x, x[j].y);
                *reinterpret_cast<__nv_bfloat162*>(&cache[k + 2]) =
                    __floats2bfloat162_rn(x[j].z, x[j].w);
            }
        }
#pragma unroll
        for (int o = 16; o; o >>= 1) {
            s_acc  += __shfl_xor_sync(0xFFFFFFFFu, s_acc, o);
            ss_acc += __shfl_xor_sync(0xFFFFFFFFu, ss_acc, o);
        }
        if (lane == 0) {
            float mu  = s_acc * (1.0f / TWO_D);
            float var = ss_acc * (1.0f / TWO_D) - mu * mu;
            s_mu[r]   = mu;
            s_rstd[r] = rsqrtf(var + EPSF);
        }
    }
    __syncthreads();

    const float mu   = s_mu[grp];
    const float rstd = s_rstd[grp];

    float acc[2][4];
#pragma unroll
    for (int nt = 0; nt < 2; nt++)
#pragma unroll
        for (int j = 0; j < 4; j++) acc[nt][j] = 0.f;

    // ---------------- K-loop: compute from smem row cache ----------------
    for (int c = 0; c < NCHUNK; c++) {
        {
            char* bd = reinterpret_cast<char*>(sB) + bn * (APAD * 2) + bq;
#pragma unroll
            for (int j = 0; j < 4; j++)
                *reinterpret_cast<uint4*>(bd + j * 16) = breg[j];
        }
        if (c + 1 < NCHUNK) {
            const char* bs = bbase + (c + 1) * (KC * 2);
#pragma unroll
            for (int j = 0; j < 4; j++)
                breg[j] = *reinterpret_cast<const uint4*>(bs + j * 16);
        }
        __syncthreads();

        const __nv_bfloat16* cache = (c < 16 ? s_u : s_p);
        const int kb = (c & 15) * KC;
#pragma unroll
        for (int s = 0; s < 4; s++) {
            const int kl = s * 16 + tig * 2;
            const int kn = c * KC + kl;
            const __nv_bfloat16* xp = &cache[grp * USTRIDE + kb + kl];
            __nv_bfloat162 x01 = *reinterpret_cast<const __nv_bfloat162*>(xp);
            __nv_bfloat162 x89 = *reinterpret_cast<const __nv_bfloat162*>(xp + 8);
            float2 gmA = *reinterpret_cast<const float2*>(gam + kn);
            float2 btA = *reinterpret_cast<const float2*>(bet + kn);
            float2 gmB = *reinterpret_cast<const float2*>(gam + kn + 8);
            float2 btB = *reinterpret_cast<const float2*>(bet + kn + 8);
            float y0 = fmaxf((__bfloat162float(x01.x) - mu) * rstd * gmA.x + btA.x, 0.f);
            float y1 = fmaxf((__bfloat162float(x01.y) - mu) * rstd * gmA.y + btA.y, 0.f);
            float y8 = fmaxf((__bfloat162float(x89.x) - mu) * rstd * gmB.x + btB.x, 0.f);
            float y9 = fmaxf((__bfloat162float(x89.y) - mu) * rstd * gmB.y + btB.y, 0.f);
            __nv_bfloat162 A01 = __floats2bfloat162_rn(y0, y1);
            __nv_bfloat162 A89 = __floats2bfloat162_rn(y8, y9);
            uint32_t a0 = *reinterpret_cast<uint32_t*>(&A01);
            uint32_t a2 = *reinterpret_cast<uint32_t*>(&A89);
#pragma unroll
            for (int nt = 0; nt < 2; nt++) {
                const __nv_bfloat16* Bb = &sB[((wid * 2 + nt) * 8 + grp) * APAD + kl];
                uint32_t b0 = *reinterpret_cast<const uint32_t*>(Bb);
                uint32_t b1 = *reinterpret_cast<const uint32_t*>(Bb + 8);
                mma16816(acc[nt], a0, a0, a2, a2, b0, b1);
            }
        }
        __syncthreads();
    }

    // ---------------- Epilogue: cross-warp gate reduce -> g ----------------
    {
        float sum = 0.f;
#pragma unroll
        for (int nt = 0; nt < 2; nt++) {
            int col = (wid * 2 + nt) * 8 + tig * 2;
            sum += sigmoidf(acc[nt][0] + s_bias[col]);
            sum += sigmoidf(acc[nt][1] + s_bias[col + 1]);
        }
        sum += __shfl_xor_sync(0xFFFFFFFFu, sum, 1);
        sum += __shfl_xor_sync(0xFFFFFFFFu, sum, 2);
        if (tig == 0) s_part[wid][grp] = sum;
    }
    __syncthreads();
    if (tid < R_TILE) {
        float tot = s_part[0][tid] + s_part[1][tid] + s_part[2][tid] + s_part[3][tid];
        float gate  = tot * (1.0f / FD);
        float logit = (*gw_p) * rsigf(gate) + g_aux_term[m0 + tid];
        float g     = sigmoidf(logit) * aux_gw[m0 + tid];
        s_g[tid] = g;
        out_g[m0 + tid] = g;
    }
    __syncthreads();

    // ---------------- Output: fp32 pair re-read * g ----------------
#pragma unroll
    for (int half = 0; half < 2; half++) {
        const int r = wid * 2 + half;
        const float g = s_g[r];
        const size_t base = (size_t)(m0 + r) * D;
        const float4* p4 = reinterpret_cast<const float4*>(pair + base);
        float4* o4 = reinterpret_cast<float4*>(out + base);
        float4 x[8];
#pragma unroll
        for (int j = 0; j < 8; j++) x[j] = p4[j * 32 + lane];
#pragma unroll
        for (int j = 0; j < 8; j++) {
            x[j].x *= g; x[j].y *= g; x[j].z *= g; x[j].w *= g;
            o4[j * 32 + lane] = x[j];
        }
    }
}

// ---------------------------------------------------------------------------
// Launch
// ---------------------------------------------------------------------------
extern "C" void kernel_launch(void* const* d_in, const int* in_sizes, int n_in,
                              void* d_out, int out_size) {
    const float* unary   = (const float*)d_in[0];
    const float* pair    = (const float*)d_in[1];
    const float* aux     = (const float*)d_in[2];
    const float* aux_gw  = (const float*)d_in[3];
    const float* ln_g    = (const float*)d_in[4];
    const float* ln_b    = (const float*)d_in[5];
    const float* W       = (const float*)d_in[6];
    const float* b       = (const float*)d_in[7];
    const float* ln_ag   = (const float*)d_in[8];
    const float* ln_ab   = (const float*)d_in[9];
    const float* W_aux   = (const float*)d_in[10];
    const float* b_aux   = (const float*)d_in[11];
    const float* gw      = (const float*)d_in[12];
    const float* agw     = (const float*)d_in[13];

    float* out   = (float*)d_out;
    float* out_g = out + (size_t)N_ROWS * D;  // outputs concatenated: (output, g)

    wconv_kernel<<<(FD * TWO_D + 255) / 256, 256>>>(W);
    aux_kernel<<<N_ROWS / 8, 256>>>(aux, ln_ag, ln_ab, W_aux, b_aux, agw);
    mega_kernel<<<N_ROWS / R_TILE, 128>>>(unary, pair, ln_g, ln_b, b, gw,
                                          aux_gw, out, out_g);
}

// round 16
// speedup vs baseline: 2.6273x; 2.6273x over previous
#include <cuda_runtime.h>
#include <cuda_bf16.h>
#include <cstdint>

// ---------------------------------------------------------------------------
// Problem constants
// ---------------------------------------------------------------------------
constexpr int N_ROWS = 32768;
constexpr int D      = 1024;
constexpr int TWO_D  = 2048;
constexpr int A_DIM  = 256;
constexpr int FD     = 64;          // gate linear out width
constexpr int M_TILE = 128;         // rows per CTA
constexpr int KC     = 64;          // k per chunk
constexpr int NCHUNK = TWO_D / KC;  // 32
constexpr int APAD   = 72;          // padded k-stride (bf16 elems) -> conflict-free
constexpr float EPSF = 1e-5f;

// ---------------------------------------------------------------------------
// Device scratch (small!)
// ---------------------------------------------------------------------------
__device__ float g_aux_term[N_ROWS];                        // agw * rsig(aux_gate)
__device__ __align__(16) __nv_bfloat16 g_Wt[FD * TWO_D];    // W^T bf16 [n][k]

// ---------------------------------------------------------------------------
// Helpers
// ---------------------------------------------------------------------------
__device__ __forceinline__ float sigmoidf(float x) { return 1.0f / (1.0f + expf(-x)); }

__device__ __forceinline__ float rsigf(float x) {
    float y = fminf(fmaxf(x, 0.001f), 0.999f);
    return logf(y) - log1pf(-y);
}

__device__ __forceinline__ void mma16816(float* c, uint32_t a0, uint32_t a1,
                                         uint32_t a2, uint32_t a3,
                                         uint32_t b0, uint32_t b1) {
    asm volatile(
        "mma.sync.aligned.m16n8k16.row.col.f32.bf16.bf16.f32 "
        "{%0,%1,%2,%3}, {%4,%5,%6,%7}, {%8,%9}, {%0,%1,%2,%3};"
        : "+f"(c[0]), "+f"(c[1]), "+f"(c[2]), "+f"(c[3])
        : "r"(a0), "r"(a1), "r"(a2), "r"(a3), "r"(b0), "r"(b1));
}

// ---------------------------------------------------------------------------
// Kernel 1: W [2048,64] fp32 -> W^T bf16 [64][2048]
// ---------------------------------------------------------------------------
__global__ void wconv_kernel(const float* __restrict__ W) {
    int idx = blockIdx.x * blockDim.x + threadIdx.x;
    if (idx >= FD * TWO_D) return;
    int n = idx >> 11;          // /2048
    int k = idx & 2047;
    g_Wt[idx] = __float2bfloat16(W[k * FD + n]);
}

// ---------------------------------------------------------------------------
// Kernel 2: aux path. Warp per row.
// ---------------------------------------------------------------------------
__global__ __launch_bounds__(256) void aux_kernel(
    const float* __restrict__ aux, const float* __restrict__ gam,
    const float* __restrict__ bet, const float* __restrict__ Wa,
    const float* __restrict__ ba, const float* __restrict__ agw_p) {
    int wid = threadIdx.x >> 5, lane = threadIdx.x & 31;
    int row = blockIdx.x * 8 + wid;
    if (row >= N_ROWS) return;

    const float4* a4 = reinterpret_cast<const float4*>(aux + (size_t)row * A_DIM);
    float4 v0 = a4[lane];
    float4 v1 = a4[32 + lane];
    float vs[8] = {v0.x, v0.y, v0.z, v0.w, v1.x, v1.y, v1.z, v1.w};

    float s = 0.f, ss = 0.f;
#pragma unroll
    for (int i = 0; i < 8; i++) { s += vs[i]; ss += vs[i] * vs[i]; }
#pragma unroll
    for (int o = 16; o; o >>= 1) {
        s  += __shfl_xor_sync(0xFFFFFFFFu, s, o);
        ss += __shfl_xor_sync(0xFFFFFFFFu, ss, o);
    }
    float mu   = s * (1.0f / A_DIM);
    float var  = ss * (1.0f / A_DIM) - mu * mu;
    float rstd = rsqrtf(var + EPSF);

    float acc[8] = {0, 0, 0, 0, 0, 0, 0, 0};
#pragma unroll
    for (int i = 0; i < 8; i++) {
        int k = (i < 4) ? (lane * 4 + i) : (128 + lane * 4 + (i - 4));
        float xh = fmaxf((vs[i] - mu) * rstd * gam[k] + bet[k], 0.f);
        const float4* w4 = reinterpret_cast<const float4*>(Wa + k * 8);
        float4 wa = w4[0], wb = w4[1];
        acc[0] += xh * wa.x; acc[1] += xh * wa.y; acc[2] += xh * wa.z; acc[3] += xh * wa.w;
        acc[4] += xh * wb.x; acc[5] += xh * wb.y; acc[6] += xh * wb.z; acc[7] += xh * wb.w;
    }
#pragma unroll
    for (int o = 16; o; o >>= 1)
#pragma unroll
        for (int j = 0; j < 8; j++)
            acc[j] += __shfl_xor_sync(0xFFFFFFFFu, acc[j], o);

    if (lane == 0) {
        float sg = 0.f;
#pragma unroll
        for (int j = 0; j < 8; j++) sg += sigmoidf(acc[j] + ba[j]);
        float aux_gate = sg * (1.0f / 8.0f);
        g_aux_term[row] = (*agw_p) * rsigf(aux_gate);
    }
}

// ---------------------------------------------------------------------------
// Kernel 3: fused main. 128 rows / CTA, 256 threads (8 warps).
//   phase 1 : LN stats, warp per row
//   K-loop  : register-prefetched staging (chunk c+1 LDGs overlap chunk c MMA)
//   epilogue: sigmoid-mean -> gate -> g; stream out = pair * g (streaming hints)
// ---------------------------------------------------------------------------
__global__ __launch_bounds__(256)
void main_kernel(const float* __restrict__ unary, const float* __restrict__ pair,
                 const float* __restrict__ gam, const float* __restrict__ bet,
                 const float* __restrict__ bias, const float* __restrict__ gw_p,
                 const float* __restrict__ aux_gw, float* __restrict__ out,
                 float* __restrict__ out_g) {
    __shared__ __align__(16) __nv_bfloat16 sA[M_TILE * APAD];  // 18432 B
    __shared__ __align__(16) __nv_bfloat16 sB[FD * APAD];      //  9216 B
    __shared__ float s_mu[M_TILE], s_rstd[M_TILE], s_g[M_TILE], s_bias[FD];

    const int tid  = threadIdx.x;
    const int wid  = tid >> 5;
    const int lane = tid & 31;
    const int m0   = blockIdx.x * M_TILE;
    const int grp  = lane >> 2;   // 0..7
    const int tig  = lane & 3;    // 0..3

    if (tid < FD) s_bias[tid] = bias[tid];

    // ---------------- Phase 1: LN stats ----------------
    for (int i = 0; i < 16; i++) {
        int r = wid * 16 + i;
        size_t row = (size_t)(m0 + r);
        const float4* u4 = reinterpret_cast<const float4*>(unary + row * D);
        const float4* p4 = reinterpret_cast<const float4*>(pair  + row * D);
        float s = 0.f, ss = 0.f;
#pragma unroll
        for (int j = 0; j < 8; j++) {
            float4 v = u4[j * 32 + lane];
            float a;
            a = fmaxf(v.x, 0.f); s += a; ss += a * a;
            a = fmaxf(v.y, 0.f); s += a; ss += a * a;
            a = fmaxf(v.z, 0.f); s += a; ss += a * a;
            a = fmaxf(v.w, 0.f); s += a; ss += a * a;
        }
#pragma unroll
        for (int j = 0; j < 8; j++) {
            float4 v = p4[j * 32 + lane];
            float a;
            a = fmaxf(v.x, 0.f); s += a; ss += a * a;
            a = fmaxf(v.y, 0.f); s += a; ss += a * a;
            a = fmaxf(v.z, 0.f); s += a; ss += a * a;
            a = fmaxf(v.w, 0.f); s += a; ss += a * a;
        }
#pragma unroll
        for (int o = 16; o; o >>= 1) {
            s  += __shfl_xor_sync(0xFFFFFFFFu, s, o);
            ss += __shfl_xor_sync(0xFFFFFFFFu, ss, o);
        }
        if (lane == 0) {
            float mu  = s * (1.0f / TWO_D);
            float var = ss * (1.0f / TWO_D) - mu * mu;
            s_mu[r]   = mu;
            s_rstd[r] = rsqrtf(var + EPSF);
        }
    }
    __syncthreads();

    // ---------------- K-loop with register prefetch ----------------
    float acc[8][4];
#pragma unroll
    for (int nt = 0; nt < 8; nt++)
#pragma unroll
        for (int j = 0; j < 4; j++) acc[nt][j] = 0.f;

    // B staging geometry: 4 threads/row, 32B each
    const int bn = tid >> 2;
    const int bq = (tid & 3) * 32;

    // Prologue: prefetch chunk 0 into registers
    float2 areg[16];
    {
        const int kk = lane * 2;   // chunk 0 -> from unary
        for (int i = 0; i < 16; i++)
            areg[i] = *reinterpret_cast<const float2*>(
                unary + (size_t)(m0 + wid * 16 + i) * D + kk);
    }
    uint4 breg0, breg1;
    {
        const char* bs = reinterpret_cast<const char*>(g_Wt) +
                         (size_t)bn * (TWO_D * 2) + bq;
        breg0 = *reinterpret_cast<const uint4*>(bs);
        breg1 = *reinterpret_cast<const uint4*>(bs + 16);
    }
    float2 gm = *reinterpret_cast<const float2*>(gam + lane * 2);
    float2 bt = *reinterpret_cast<const float2*>(bet + lane * 2);

    for (int c = 0; c < NCHUNK; c++) {
        // ---- STS phase: consume registers for chunk c ----
        {
            char* bd = reinterpret_cast<char*>(sB) + bn * (APAD * 2) + bq;
            *reinterpret_cast<uint4*>(bd)      = breg0;
            *reinterpret_cast<uint4*>(bd + 16) = breg1;
        }
        for (int i = 0; i < 16; i++) {
            int r = wid * 16 + i;
            float mu = s_mu[r], rstd = s_rstd[r];
            float x0 = fmaxf(areg[i].x, 0.f), x1 = fmaxf(areg[i].y, 0.f);
            float y0 = fmaxf((x0 - mu) * rstd * gm.x + bt.x, 0.f);
            float y1 = fmaxf((x1 - mu) * rstd * gm.y + bt.y, 0.f);
            *reinterpret_cast<__nv_bfloat162*>(&sA[r * APAD + lane * 2]) =
                __floats2bfloat162_rn(y0, y1);
        }

        // ---- Prefetch chunk c+1 (LDGs overlap the MMA below) ----
        if (c + 1 < NCHUNK) {
            const int kn = (c + 1) * KC + lane * 2;
            const bool fu = (kn < D);
            const float* base = fu ? unary : pair;
            const int kr = fu ? kn : (kn - D);
            for (int i = 0; i < 16; i++)
                areg[i] = *reinterpret_cast<const float2*>(
                    base + (size_t)(m0 + wid * 16 + i) * D + kr);
            const char* bs = reinterpret_cast<const char*>(g_Wt) +
                             (size_t)bn * (TWO_D * 2) + (c + 1) * (KC * 2) + bq;
            breg0 = *reinterpret_cast<const uint4*>(bs);
            breg1 = *reinterpret_cast<const uint4*>(bs + 16);
            gm = *reinterpret_cast<const float2*>(gam + kn);
            bt = *reinterpret_cast<const float2*>(bet + kn);
        }
        __syncthreads();

        // ---- MMA: warp w owns rows 16w..16w+15; 4 k-steps x 8 n-tiles ----
        const __nv_bfloat16* Abase = &sA[(wid * 16 + grp) * APAD];
#pragma unroll
        for (int s = 0; s < 4; s++) {
            int kl = s * 16 + tig * 2;
            uint32_t a0 = *reinterpret_cast<const uint32_t*>(Abase + kl);
            uint32_t a1 = *reinterpret_cast<const uint32_t*>(Abase + 8 * APAD + kl);
            uint32_t a2 = *reinterpret_cast<const uint32_t*>(Abase + kl + 8);
            uint32_t a3 = *reinterpret_cast<const uint32_t*>(Abase + 8 * APAD + kl + 8);
#pragma unroll
            for (int nt = 0; nt < 8; nt++) {
                const __nv_bfloat16* Bb = &sB[(nt * 8 + grp) * APAD + kl];
                uint32_t b0 = *reinterpret_cast<const uint32_t*>(Bb);
                uint32_t b1 = *reinterpret_cast<const uint32_t*>(Bb + 8);
                mma16816(acc[nt], a0, a1, a2, a3, b0, b1);
            }
        }
        __syncthreads();
    }

    // ---------------- Epilogue: gate -> g ----------------
    {
        float sum0 = 0.f, sum1 = 0.f;
#pragma unroll
        for (int nt = 0; nt < 8; nt++) {
            int col = nt * 8 + tig * 2;
            float b0 = s_bias[col], b1 = s_bias[col + 1];
            sum0 += sigmoidf(acc[nt][0] + b0) + sigmoidf(acc[nt][1] + b1);
            sum1 += sigmoidf(acc[nt][2] + b0) + sigmoidf(acc[nt][3] + b1);
        }
        sum0 += __shfl_xor_sync(0xFFFFFFFFu, sum0, 1);
        sum0 += __shfl_xor_sync(0xFFFFFFFFu, sum0, 2);
        sum1 += __shfl_xor_sync(0xFFFFFFFFu, sum1, 1);
        sum1 += __shfl_xor_sync(0xFFFFFFFFu, sum1, 2);
        if (tig == 0) {
            float gwv = *gw_p;
#pragma unroll
            for (int h = 0; h < 2; h++) {
                int r = wid * 16 + grp + h * 8;
                float gate  = (h ? sum1 : sum0) * (1.0f / FD);
                float logit = gwv * rsigf(gate) + g_aux_term[m0 + r];
                float g     = sigmoidf(logit) * aux_gw[m0 + r];
                s_g[r] = g;
                out_g[m0 + r] = g;
            }
        }
    }
    __syncthreads();

    // ---------------- Output stream: out = pair * g ----------------
    // __ldcs: evict-first read (pair bytes are dead after this);
    // __stcs: streaming store (no L2 read-allocate pollution).
    for (int i = 0; i < 16; i++) {
        int r = wid * 16 + i;
        float g = s_g[r];
        size_t base = (size_t)(m0 + r) * D;
        const float4* p4 = reinterpret_cast<const float4*>(pair + base);
        float4* o4 = reinterpret_cast<float4*>(out + base);
#pragma unroll
        for (int j = 0; j < 8; j++) {
            float4 v = __ldcs(p4 + j * 32 + lane);
            v.x *= g; v.y *= g; v.z *= g; v.w *= g;
            __stcs(o4 + j * 32 + lane, v);
        }
    }
}

// ---------------------------------------------------------------------------
// Launch
// ---------------------------------------------------------------------------
extern "C" void kernel_launch(void* const* d_in, const int* in_sizes, int n_in,
                              void* d_out, int out_size) {
    const float* unary   = (const float*)d_in[0];
    const float* pair    = (const float*)d_in[1];
    const float* aux     = (const float*)d_in[2];
    const float* aux_gw  = (const float*)d_in[3];
    const float* ln_g    = (const float*)d_in[4];
    const float* ln_b    = (const float*)d_in[5];
    const float* W       = (const float*)d_in[6];
    const float* b       = (const float*)d_in[7];
    const float* ln_ag   = (const float*)d_in[8];
    const float* ln_ab   = (const float*)d_in[9];
    const float* W_aux   = (const float*)d_in[10];
    const float* b_aux   = (const float*)d_in[11];
    const float* gw      = (const float*)d_in[12];
    const float* agw     = (const float*)d_in[13];

    float* out   = (float*)d_out;
    float* out_g = out + (size_t)N_ROWS * D;  // outputs concatenated: (output, g)

    wconv_kernel<<<(FD * TWO_D + 255) / 256, 256>>>(W);
    aux_kernel<<<N_ROWS / 8, 256>>>(aux, ln_ag, ln_ab, W_aux, b_aux, agw);
    main_kernel<<<N_ROWS / M_TILE, 256>>>(unary, pair, ln_g, ln_b, b, gw,
                                          aux_gw, out, out_g);
}

// round 17
// speedup vs baseline: 2.9571x; 1.1255x over previous
#include <cuda_runtime.h>
#include <cuda_bf16.h>
#include <cstdint>

// ---------------------------------------------------------------------------
// Problem constants
// ---------------------------------------------------------------------------
constexpr int N_ROWS = 32768;
constexpr int D      = 1024;
constexpr int TWO_D  = 2048;
constexpr int A_DIM  = 256;
constexpr int FD     = 64;          // gate linear out width
constexpr int M_TILE = 128;         // rows per CTA
constexpr int KC     = 64;          // k per chunk
constexpr int NCHUNK = TWO_D / KC;  // 32
constexpr int APAD   = 72;          // padded k-stride (bf16 elems) -> conflict-free
constexpr float EPSF = 1e-5f;

// ---------------------------------------------------------------------------
// Device scratch (small!)
// ---------------------------------------------------------------------------
__device__ float g_aux_term[N_ROWS];                        // agw * rsig(aux_gate)
__device__ __align__(16) __nv_bfloat16 g_Wt[FD * TWO_D];    // W^T bf16 [n][k]

// ---------------------------------------------------------------------------
// Helpers
// ---------------------------------------------------------------------------
__device__ __forceinline__ float sigmoidf(float x) { return 1.0f / (1.0f + expf(-x)); }

__device__ __forceinline__ float rsigf(float x) {
    float y = fminf(fmaxf(x, 0.001f), 0.999f);
    return logf(y) - log1pf(-y);
}

__device__ __forceinline__ void mma16816(float* c, uint32_t a0, uint32_t a1,
                                         uint32_t a2, uint32_t a3,
                                         uint32_t b0, uint32_t b1) {
    asm volatile(
        "mma.sync.aligned.m16n8k16.row.col.f32.bf16.bf16.f32 "
        "{%0,%1,%2,%3}, {%4,%5,%6,%7}, {%8,%9}, {%0,%1,%2,%3};"
        : "+f"(c[0]), "+f"(c[1]), "+f"(c[2]), "+f"(c[3])
        : "r"(a0), "r"(a1), "r"(a2), "r"(a3), "r"(b0), "r"(b1));
}

// ---------------------------------------------------------------------------
// Kernel 1: W [2048,64] fp32 -> W^T bf16 [64][2048]
// ---------------------------------------------------------------------------
__global__ void wconv_kernel(const float* __restrict__ W) {
    int idx = blockIdx.x * blockDim.x + threadIdx.x;
    if (idx >= FD * TWO_D) return;
    int n = idx >> 11;          // /2048
    int k = idx & 2047;
    g_Wt[idx] = __float2bfloat16(W[k * FD + n]);
}

// ---------------------------------------------------------------------------
// Kernel 2: aux path. Warp per row.
// ---------------------------------------------------------------------------
__global__ __launch_bounds__(256) void aux_kernel(
    const float* __restrict__ aux, const float* __restrict__ gam,
    const float* __restrict__ bet, const float* __restrict__ Wa,
    const float* __restrict__ ba, const float* __restrict__ agw_p) {
    int wid = threadIdx.x >> 5, lane = threadIdx.x & 31;
    int row = blockIdx.x * 8 + wid;
    if (row >= N_ROWS) return;

    const float4* a4 = reinterpret_cast<const float4*>(aux + (size_t)row * A_DIM);
    float4 v0 = a4[lane];
    float4 v1 = a4[32 + lane];
    float vs[8] = {v0.x, v0.y, v0.z, v0.w, v1.x, v1.y, v1.z, v1.w};

    float s = 0.f, ss = 0.f;
#pragma unroll
    for (int i = 0; i < 8; i++) { s += vs[i]; ss += vs[i] * vs[i]; }
#pragma unroll
    for (int o = 16; o; o >>= 1) {
        s  += __shfl_xor_sync(0xFFFFFFFFu, s, o);
        ss += __shfl_xor_sync(0xFFFFFFFFu, ss, o);
    }
    float mu   = s * (1.0f / A_DIM);
    float var  = ss * (1.0f / A_DIM) - mu * mu;
    float rstd = rsqrtf(var + EPSF);

    float acc[8] = {0, 0, 0, 0, 0, 0, 0, 0};
#pragma unroll
    for (int i = 0; i < 8; i++) {
        int k = (i < 4) ? (lane * 4 + i) : (128 + lane * 4 + (i - 4));
        float xh = fmaxf((vs[i] - mu) * rstd * gam[k] + bet[k], 0.f);
        const float4* w4 = reinterpret_cast<const float4*>(Wa + k * 8);
        float4 wa = w4[0], wb = w4[1];
        acc[0] += xh * wa.x; acc[1] += xh * wa.y; acc[2] += xh * wa.z; acc[3] += xh * wa.w;
        acc[4] += xh * wb.x; acc[5] += xh * wb.y; acc[6] += xh * wb.z; acc[7] += xh * wb.w;
    }
#pragma unroll
    for (int o = 16; o; o >>= 1)
#pragma unroll
        for (int j = 0; j < 8; j++)
            acc[j] += __shfl_xor_sync(0xFFFFFFFFu, acc[j], o);

    if (lane == 0) {
        float sg = 0.f;
#pragma unroll
        for (int j = 0; j < 8; j++) sg += sigmoidf(acc[j] + ba[j]);
        float aux_gate = sg * (1.0f / 8.0f);
        g_aux_term[row] = (*agw_p) * rsigf(aux_gate);
    }
}

// ---------------------------------------------------------------------------
// Kernel 3: fused main. 128 rows / CTA, 256 threads (8 warps).
//   phase 1 : LN stats, warp per row
//   K-loop  : register-prefetched staging (chunk c+1 LDGs overlap chunk c MMA)
//   epilogue: sigmoid-mean -> gate -> g; stream out = pair * g
// ---------------------------------------------------------------------------
__global__ __launch_bounds__(256)
void main_kernel(const float* __restrict__ unary, const float* __restrict__ pair,
                 const float* __restrict__ gam, const float* __restrict__ bet,
                 const float* __restrict__ bias, const float* __restrict__ gw_p,
                 const float* __restrict__ aux_gw, float* __restrict__ out,
                 float* __restrict__ out_g) {
    __shared__ __align__(16) __nv_bfloat16 sA[M_TILE * APAD];  // 18432 B
    __shared__ __align__(16) __nv_bfloat16 sB[FD * APAD];      //  9216 B
    __shared__ float s_mu[M_TILE], s_rstd[M_TILE], s_g[M_TILE], s_bias[FD];

    const int tid  = threadIdx.x;
    const int wid  = tid >> 5;
    const int lane = tid & 31;
    const int m0   = blockIdx.x * M_TILE;
    const int grp  = lane >> 2;   // 0..7
    const int tig  = lane & 3;    // 0..3

    if (tid < FD) s_bias[tid] = bias[tid];

    // ---------------- Phase 1: LN stats ----------------
    for (int i = 0; i < 16; i++) {
        int r = wid * 16 + i;
        size_t row = (size_t)(m0 + r);
        const float4* u4 = reinterpret_cast<const float4*>(unary + row * D);
        const float4* p4 = reinterpret_cast<const float4*>(pair  + row * D);
        float s = 0.f, ss = 0.f;
#pragma unroll
        for (int j = 0; j < 8; j++) {
            float4 v = u4[j * 32 + lane];
            float a;
            a = fmaxf(v.x, 0.f); s += a; ss += a * a;
            a = fmaxf(v.y, 0.f); s += a; ss += a * a;
            a = fmaxf(v.z, 0.f); s += a; ss += a * a;
            a = fmaxf(v.w, 0.f); s += a; ss += a * a;
        }
#pragma unroll
        for (int j = 0; j < 8; j++) {
            float4 v = p4[j * 32 + lane];
            float a;
            a = fmaxf(v.x, 0.f); s += a; ss += a * a;
            a = fmaxf(v.y, 0.f); s += a; ss += a * a;
            a = fmaxf(v.z, 0.f); s += a; ss += a * a;
            a = fmaxf(v.w, 0.f); s += a; ss += a * a;
        }
#pragma unroll
        for (int o = 16; o; o >>= 1) {
            s  += __shfl_xor_sync(0xFFFFFFFFu, s, o);
            ss += __shfl_xor_sync(0xFFFFFFFFu, ss, o);
        }
        if (lane == 0) {
            float mu  = s * (1.0f / TWO_D);
            float var = ss * (1.0f / TWO_D) - mu * mu;
            s_mu[r]   = mu;
            s_rstd[r] = rsqrtf(var + EPSF);
        }
    }
    __syncthreads();

    // ---------------- K-loop with register prefetch ----------------
    float acc[8][4];
#pragma unroll
    for (int nt = 0; nt < 8; nt++)
#pragma unroll
        for (int j = 0; j < 4; j++) acc[nt][j] = 0.f;

    // B staging geometry: 4 threads/row, 32B each
    const int bn = tid >> 2;
    const int bq = (tid & 3) * 32;

    // Prologue: prefetch chunk 0 into registers
    float2 areg[16];
    {
        const int kk = lane * 2;   // chunk 0 -> from unary
        for (int i = 0; i < 16; i++)
            areg[i] = *reinterpret_cast<const float2*>(
                unary + (size_t)(m0 + wid * 16 + i) * D + kk);
    }
    uint4 breg0, breg1;
    {
        const char* bs = reinterpret_cast<const char*>(g_Wt) +
                         (size_t)bn * (TWO_D * 2) + bq;
        breg0 = *reinterpret_cast<const uint4*>(bs);
        breg1 = *reinterpret_cast<const uint4*>(bs + 16);
    }
    float2 gm = *reinterpret_cast<const float2*>(gam + lane * 2);
    float2 bt = *reinterpret_cast<const float2*>(bet + lane * 2);

    for (int c = 0; c < NCHUNK; c++) {
        // ---- STS phase: consume registers for chunk c ----
        {
            char* bd = reinterpret_cast<char*>(sB) + bn * (APAD * 2) + bq;
            *reinterpret_cast<uint4*>(bd)      = breg0;
            *reinterpret_cast<uint4*>(bd + 16) = breg1;
        }
        for (int i = 0; i < 16; i++) {
            int r = wid * 16 + i;
            float mu = s_mu[r], rstd = s_rstd[r];
            float x0 = fmaxf(areg[i].x, 0.f), x1 = fmaxf(areg[i].y, 0.f);
            float y0 = fmaxf((x0 - mu) * rstd * gm.x + bt.x, 0.f);
            float y1 = fmaxf((x1 - mu) * rstd * gm.y + bt.y, 0.f);
            *reinterpret_cast<__nv_bfloat162*>(&sA[r * APAD + lane * 2]) =
                __floats2bfloat162_rn(y0, y1);
        }

        // ---- Prefetch chunk c+1 (LDGs overlap the MMA below) ----
        if (c + 1 < NCHUNK) {
            const int kn = (c + 1) * KC + lane * 2;
            const bool fu = (kn < D);
            const float* base = fu ? unary : pair;
            const int kr = fu ? kn : (kn - D);
            for (int i = 0; i < 16; i++)
                areg[i] = *reinterpret_cast<const float2*>(
                    base + (size_t)(m0 + wid * 16 + i) * D + kr);
            const char* bs = reinterpret_cast<const char*>(g_Wt) +
                             (size_t)bn * (TWO_D * 2) + (c + 1) * (KC * 2) + bq;
            breg0 = *reinterpret_cast<const uint4*>(bs);
            breg1 = *reinterpret_cast<const uint4*>(bs + 16);
            gm = *reinterpret_cast<const float2*>(gam + kn);
            bt = *reinterpret_cast<const float2*>(bet + kn);
        }
        __syncthreads();

        // ---- MMA: warp w owns rows 16w..16w+15; 4 k-steps x 8 n-tiles ----
        const __nv_bfloat16* Abase = &sA[(wid * 16 + grp) * APAD];
#pragma unroll
        for (int s = 0; s < 4; s++) {
            int kl = s * 16 + tig * 2;
            uint32_t a0 = *reinterpret_cast<const uint32_t*>(Abase + kl);
            uint32_t a1 = *reinterpret_cast<const uint32_t*>(Abase + 8 * APAD + kl);
            uint32_t a2 = *reinterpret_cast<const uint32_t*>(Abase + kl + 8);
            uint32_t a3 = *reinterpret_cast<const uint32_t*>(Abase + 8 * APAD + kl + 8);
#pragma unroll
            for (int nt = 0; nt < 8; nt++) {
                const __nv_bfloat16* Bb = &sB[(nt * 8 + grp) * APAD + kl];
                uint32_t b0 = *reinterpret_cast<const uint32_t*>(Bb);
                uint32_t b1 = *reinterpret_cast<const uint32_t*>(Bb + 8);
                mma16816(acc[nt], a0, a1, a2, a3, b0, b1);
            }
        }
        __syncthreads();
    }

    // ---------------- Epilogue: gate -> g ----------------
    {
        float sum0 = 0.f, sum1 = 0.f;
#pragma unroll
        for (int nt = 0; nt < 8; nt++) {
            int col = nt * 8 + tig * 2;
            float b0 = s_bias[col], b1 = s_bias[col + 1];
            sum0 += sigmoidf(acc[nt][0] + b0) + sigmoidf(acc[nt][1] + b1);
            sum1 += sigmoidf(acc[nt][2] + b0) + sigmoidf(acc[nt][3] + b1);
        }
        sum0 += __shfl_xor_sync(0xFFFFFFFFu, sum0, 1);
        sum0 += __shfl_xor_sync(0xFFFFFFFFu, sum0, 2);
        sum1 += __shfl_xor_sync(0xFFFFFFFFu, sum1, 1);
        sum1 += __shfl_xor_sync(0xFFFFFFFFu, sum1, 2);
        if (tig == 0) {
            float gwv = *gw_p;
#pragma unroll
            for (int h = 0; h < 2; h++) {
                int r = wid * 16 + grp + h * 8;
                float gate  = (h ? sum1 : sum0) * (1.0f / FD);
                float logit = gwv * rsigf(gate) + g_aux_term[m0 + r];
                float g     = sigmoidf(logit) * aux_gw[m0 + r];
                s_g[r] = g;
                out_g[m0 + r] = g;
            }
        }
    }
    __syncthreads();

    // ---------------- Output stream: out = pair * g ----------------
    for (int i = 0; i < 16; i++) {
        int r = wid * 16 + i;
        float g = s_g[r];
        size_t base = (size_t)(m0 + r) * D;
        const float4* p4 = reinterpret_cast<const float4*>(pair + base);
        float4* o4 = reinterpret_cast<float4*>(out + base);
#pragma unroll
        for (int j = 0; j < 8; j++) {
            float4 v = p4[j * 32 + lane];
            v.x *= g; v.y *= g; v.z *= g; v.w *= g;
            o4[j * 32 + lane] = v;
        }
    }
}

// ---------------------------------------------------------------------------
// Launch
// ---------------------------------------------------------------------------
extern "C" void kernel_launch(void* const* d_in, const int* in_sizes, int n_in,
                              void* d_out, int out_size) {
    const float* unary   = (const float*)d_in[0];
    const float* pair    = (const float*)d_in[1];
    const float* aux     = (const float*)d_in[2];
    const float* aux_gw  = (const float*)d_in[3];
    const float* ln_g    = (const float*)d_in[4];
    const float* ln_b    = (const float*)d_in[5];
    const float* W       = (const float*)d_in[6];
    const float* b       = (const float*)d_in[7];
    const float* ln_ag   = (const float*)d_in[8];
    const float* ln_ab   = (const float*)d_in[9];
    const float* W_aux   = (const float*)d_in[10];
    const float* b_aux   = (const float*)d_in[11];
    const float* gw      = (const float*)d_in[12];
    const float* agw     = (const float*)d_in[13];

    float* out   = (float*)d_out;
    float* out_g = out + (size_t)N_ROWS * D;  // outputs concatenated: (output, g)

    wconv_kernel<<<(FD * TWO_D + 255) / 256, 256>>>(W);
    aux_kernel<<<N_ROWS / 8, 256>>>(aux, ln_ag, ln_ab, W_aux, b_aux, agw);
    main_kernel<<<N_ROWS / M_TILE, 256>>>(unary, pair, ln_g, ln_b, b, gw,
                                          aux_gw, out, out_g);
}